// round 9
// baseline (speedup 1.0000x reference)
#include <cuda_runtime.h>

// StackedLSTM: B=2048, T=2048, D=H=6, 2 layers, softmax over final h of layer 1.
// 8 lanes per batch: lanes 0-2 run layer 0 (units {2u,2u+1}), lanes 4-6 layer 1,
// lanes 3/7 idle padding. 1-step layer skew. Each lane computes 8 gate rows
// (k-pair packed f32x2 FFMA). State exchanged as packed {h_even,h_odd} u64 via
// 64-bit shuffles (12 SHFL/iter). 1 warp per SMSP (512 warps total), weights in
// registers with sigmoid 0.5-prescale folded in, x double-buffered in registers.

#define TT 2048

typedef unsigned long long u64;
typedef ulonglong2 u64x2;

__device__ __forceinline__ u64 pack2(float lo, float hi) {
    u64 r; asm("mov.b64 %0, {%1, %2};" : "=l"(r) : "f"(lo), "f"(hi)); return r;
}
__device__ __forceinline__ void unpack2(u64 v, float& lo, float& hi) {
    asm("mov.b64 {%0, %1}, %2;" : "=f"(lo), "=f"(hi) : "l"(v));
}
__device__ __forceinline__ u64 ffma2(u64 a, u64 b, u64 c) {
    u64 d; asm("fma.rn.f32x2 %0, %1, %2, %3;" : "=l"(d) : "l"(a), "l"(b), "l"(c));
    return d;
}
__device__ __forceinline__ u64 fadd2(u64 a, u64 b) {
    u64 d; asm("add.rn.f32x2 %0, %1, %2;" : "=l"(d) : "l"(a), "l"(b)); return d;
}
__device__ __forceinline__ float tanh_f(float x) {
    float y; asm("tanh.approx.f32 %0, %1;" : "=f"(y) : "f"(x)); return y;
}

struct LaneW {
    u64 wx[8][3];   // 8 gate rows (4 gates x 2 units), input-side k-pair weights
    u64 wh[8][3];   // recurrent-side k-pair weights
    u64 b[8];       // {bias, 0} accumulator seeds
};

// One LSTM step for this lane's TWO hidden units.
// in[3]/rg[3]: k-pair packed {v2k, v2k+1} input / recurrent vectors.
// Rows 0..3 = gates (i,f,g,o) of unit a; rows 4..7 = unit b.
__device__ __forceinline__ void cell2(const LaneW& W, const u64* in, const u64* rg,
                                      float& ha, float& ca, float& hb, float& cb) {
    float g[8];
#pragma unroll
    for (int r = 0; r < 8; ++r) {
        u64 a0 = ffma2(W.wx[r][0], in[0], W.b[r]);
        a0     = ffma2(W.wx[r][1], in[1], a0);
        a0     = ffma2(W.wx[r][2], in[2], a0);
        u64 a1 = ffma2(W.wh[r][0], rg[0], 0ull);
        a1     = ffma2(W.wh[r][1], rg[1], a1);
        a1     = ffma2(W.wh[r][2], rg[2], a1);
        u64 s2 = fadd2(a0, a1);
        float lo, hi; unpack2(s2, lo, hi);
        g[r] = lo + hi;
    }
    // sigmoid gates (i,f,o) prescaled by 0.5: sig = .5 + .5*tanh(prescaled)
    float ia = fmaf(tanh_f(g[0]), 0.5f, 0.5f);
    float fa = fmaf(tanh_f(g[1]), 0.5f, 0.5f);
    float ga = tanh_f(g[2]);
    float oa = fmaf(tanh_f(g[3]), 0.5f, 0.5f);
    float ib = fmaf(tanh_f(g[4]), 0.5f, 0.5f);
    float fb = fmaf(tanh_f(g[5]), 0.5f, 0.5f);
    float gb = tanh_f(g[6]);
    float ob = fmaf(tanh_f(g[7]), 0.5f, 0.5f);
    ca = fmaf(fa, ca, ia * ga);
    cb = fmaf(fb, cb, ib * gb);
    ha = oa * tanh_f(ca);
    hb = ob * tanh_f(cb);
}

// One fused iteration. hp: this lane's packed {h_a,h_b}. rsel: own-layer source
// base lane; base: layer-0 source base. 12 SHFL total (6 x 64-bit).
template <bool ZF>
__device__ __forceinline__ void iter(const LaneW& W, bool isL1, int rsel, int base,
                                     const u64* xp, u64& hp,
                                     float& ha, float& ca, float& hb, float& cb) {
    u64 rg[3], h0[3];
#pragma unroll
    for (int k = 0; k < 3; ++k)
        rg[k] = __shfl_sync(0xffffffffu, hp, rsel + k);   // own-layer recurrence
#pragma unroll
    for (int k = 0; k < 3; ++k)
        h0[k] = __shfl_sync(0xffffffffu, hp, base + k);   // layer-0 state (L1 input)
    u64 in[3] = { isL1 ? h0[0] : xp[0], isL1 ? h0[1] : xp[1], isL1 ? h0[2] : xp[2] };
    cell2(W, in, rg, ha, ca, hb, cb);
    if (ZF && isL1) { ha = 0.f; ca = 0.f; hb = 0.f; cb = 0.f; }  // iter 0: L1 spurious
    hp = pack2(ha, hb);
}

// 4 timesteps from one x block (12 u64 = 24 floats = 4 steps).
template <bool ZF>
__device__ __forceinline__ void steps4(const LaneW& W, bool isL1, int rsel, int base,
                                       const u64* u, u64& hp,
                                       float& ha, float& ca, float& hb, float& cb) {
    iter<ZF>   (W, isL1, rsel, base, u + 0, hp, ha, ca, hb, cb);
    iter<false>(W, isL1, rsel, base, u + 3, hp, ha, ca, hb, cb);
    iter<false>(W, isL1, rsel, base, u + 6, hp, ha, ca, hb, cb);
    iter<false>(W, isL1, rsel, base, u + 9, hp, ha, ca, hb, cb);
}

__device__ __forceinline__ void loadblk(const float* __restrict__ xb, int m, u64* u) {
    const u64x2* p = (const u64x2*)(xb + 24 * m);   // 96B block, 16B aligned
#pragma unroll
    for (int i = 0; i < 6; ++i) { u64x2 v = p[i]; u[2 * i] = v.x; u[2 * i + 1] = v.y; }
}

__global__ void __launch_bounds__(128, 1)
stacked_lstm_kernel(const float* __restrict__ x,
                    const float* __restrict__ Wi0, const float* __restrict__ Wh0,
                    const float* __restrict__ bi0, const float* __restrict__ bh0,
                    const float* __restrict__ Wi1, const float* __restrict__ Wh1,
                    const float* __restrict__ bi1, const float* __restrict__ bh1,
                    float* __restrict__ out) {
    const int lane  = threadIdx.x & 31;
    const int l8    = lane & 7;             // position within 8-lane batch group
    const bool isL1 = (l8 & 4) != 0;        // lanes 4-6: layer 1
    const int u     = l8 & 3;               // unit-pair index (0..2 active, 3 idle)
    const int uu    = (u < 3) ? u : 2;      // clamp for safe weight loads
    const int base  = lane & ~7;            // group base lane (layer-0 lanes)
    const int rsel  = isL1 ? base + 4 : base;  // own-layer source base
    const int b     = (blockIdx.x * blockDim.x + threadIdx.x) >> 3;   // batch

    // Per-lane weight set.
    const float* Wi = isL1 ? Wi1 : Wi0;
    const float* Wh = isL1 ? Wh1 : Wh0;
    const float* bi = isL1 ? bi1 : bi0;
    const float* bh = isL1 ? bh1 : bh0;

    // PyTorch gate rows: i=[0:6) f=[6:12) g=[12:18) o=[18:24).
    // This lane covers units {2uu, 2uu+1}: rows goff[q]+2uu (unit a) and +1 (unit b).
    LaneW W;
    const int   goff[4] = {0, 6, 12, 18};
    const float gscl[4] = {0.5f, 0.5f, 1.0f, 0.5f};
#pragma unroll
    for (int q = 0; q < 4; ++q) {
        const float s  = gscl[q];
        const int   ra = goff[q] + 2 * uu;      // unit a row
        const int   rb = ra + 1;                // unit b row
#pragma unroll
        for (int p = 0; p < 3; ++p) {
            W.wx[q][p]     = pack2(s * Wi[ra * 6 + 2 * p], s * Wi[ra * 6 + 2 * p + 1]);
            W.wx[q + 4][p] = pack2(s * Wi[rb * 6 + 2 * p], s * Wi[rb * 6 + 2 * p + 1]);
            W.wh[q][p]     = pack2(s * Wh[ra * 6 + 2 * p], s * Wh[ra * 6 + 2 * p + 1]);
            W.wh[q + 4][p] = pack2(s * Wh[rb * 6 + 2 * p], s * Wh[rb * 6 + 2 * p + 1]);
        }
        W.b[q]     = pack2(s * (bi[ra] + bh[ra]), 0.f);
        W.b[q + 4] = pack2(s * (bi[rb] + bh[rb]), 0.f);
    }

    const float* xb = x + (size_t)b * TT * 6;

    float ha = 0.f, ca = 0.f, hb = 0.f, cb = 0.f;
    u64 hp = 0ull;                    // packed {h_a, h_b}

    u64 A[12], B[12];                 // x double buffer: 4 timesteps per block
    loadblk(xb, 0, B);
    loadblk(xb, 1, A);

    steps4<true>(W, isL1, rsel, base, B, hp, ha, ca, hb, cb);   // block 0 (zero-fix)

#pragma unroll 1
    for (int m = 1; m < 511; m += 2) {
        loadblk(xb, m + 1, B);
        steps4<false>(W, isL1, rsel, base, A, hp, ha, ca, hb, cb);   // block m
        loadblk(xb, m + 2, A);
        steps4<false>(W, isL1, rsel, base, B, hp, ha, ca, hb, cb);   // block m+1
    }
    steps4<false>(W, isL1, rsel, base, A, hp, ha, ca, hb, cb);       // block 511

    // Epilogue iteration 2048: layer 1 consumes h0(2047); L0 computes unused junk.
    {
        u64 z[3] = {0ull, 0ull, 0ull};
        iter<false>(W, isL1, rsel, base, z, hp, ha, ca, hb, cb);
    }

    // Final layer-1 h pairs live on lanes base+4+kp (kp=0..2). Gather + softmax.
    float hv[6];
#pragma unroll
    for (int kp = 0; kp < 3; ++kp) {
        u64 p = __shfl_sync(0xffffffffu, hp, base + 4 + kp);
        unpack2(p, hv[2 * kp], hv[2 * kp + 1]);
    }
    float mx = hv[0];
#pragma unroll
    for (int k = 1; k < 6; ++k) mx = fmaxf(mx, hv[k]);
    float s = 0.f, ev[6];
#pragma unroll
    for (int k = 0; k < 6; ++k) { ev[k] = __expf(hv[k] - mx); s += ev[k]; }
    if (isL1 && u < 3) {
        float inv = __fdividef(1.0f, s);
        float2 o2 = make_float2(ev[2 * u] * inv, ev[2 * u + 1] * inv);
        *(float2*)(out + (size_t)b * 6 + 2 * u) = o2;   // 8B aligned
    }
}

extern "C" void kernel_launch(void* const* d_in, const int* in_sizes, int n_in,
                              void* d_out, int out_size) {
    (void)in_sizes; (void)n_in; (void)out_size;
    const float* x   = (const float*)d_in[0];
    const float* Wi0 = (const float*)d_in[1];
    const float* Wh0 = (const float*)d_in[2];
    const float* bi0 = (const float*)d_in[3];
    const float* bh0 = (const float*)d_in[4];
    const float* Wi1 = (const float*)d_in[5];
    const float* Wh1 = (const float*)d_in[6];
    const float* bi1 = (const float*)d_in[7];
    const float* bh1 = (const float*)d_in[8];
    float* out = (float*)d_out;

    // 2048 batches * 8 lanes = 16384 threads = 128 blocks x 128 threads:
    // 1 block/SM on 128 SMs, exactly 1 warp per SMSP (zero co-residency).
    stacked_lstm_kernel<<<128, 128>>>(x, Wi0, Wh0, bi0, bh0, Wi1, Wh1, bi1, bh1, out);
}